// round 4
// baseline (speedup 1.0000x reference)
#include <cuda_runtime.h>
#include <math.h>

// ChannelAttention — R4: two-kernel split.
//   Kernel A: streaming pool (mean+max) — one warp per (blk, channel).
//             131072 warps, 8x LDG.128 per warp, zero smem/barriers/tail.
//   Kernel B: grouped MLP sigmoid( relu(pm@W1')@W2' + relu(px@W1')@W2' ).
// x  : [B=8, O=8, S=32, C=64, 32, 32] fp32 (512 MB)
// w1 : [8,64,64], w2 : [8,64,64] fp32
// out: [B,O,S,C] fp32

#define C_DIM   64
#define HW_DIM  1024
#define O_DIM   8
#define S_DIM   32
#define NBLK    2048            // B*O*S

// scratch for pooled values (allocation-free per harness rules)
__device__ float g_pm[NBLK * C_DIM];
__device__ float g_px[NBLK * C_DIM];

// ---------------- Kernel A: pooling ----------------
// block = 256 threads (8 warps), grid = NBLK*C_DIM/8 = 16384
__global__ __launch_bounds__(256, 6)
void pool_kernel(const float* __restrict__ x)
{
    const int lane = threadIdx.x & 31;
    const int gw   = blockIdx.x * 8 + (threadIdx.x >> 5);  // global warp id
    // gw in [0, NBLK*C_DIM): row = (blk, c)
    const float4* row = reinterpret_cast<const float4*>(x) + (size_t)gw * (HW_DIM / 4) + lane;

    float4 v0 = __ldcs(row + 0 * 32);
    float4 v1 = __ldcs(row + 1 * 32);
    float4 v2 = __ldcs(row + 2 * 32);
    float4 v3 = __ldcs(row + 3 * 32);
    float4 v4 = __ldcs(row + 4 * 32);
    float4 v5 = __ldcs(row + 5 * 32);
    float4 v6 = __ldcs(row + 6 * 32);
    float4 v7 = __ldcs(row + 7 * 32);

    // 4 independent accumulation chains
    float sa = (v0.x + v0.y) + (v0.z + v0.w);
    float sb = (v1.x + v1.y) + (v1.z + v1.w);
    float sc = (v2.x + v2.y) + (v2.z + v2.w);
    float sd = (v3.x + v3.y) + (v3.z + v3.w);
    sa += (v4.x + v4.y) + (v4.z + v4.w);
    sb += (v5.x + v5.y) + (v5.z + v5.w);
    sc += (v6.x + v6.y) + (v6.z + v6.w);
    sd += (v7.x + v7.y) + (v7.z + v7.w);

    float ma = fmaxf(fmaxf(v0.x, v0.y), fmaxf(v0.z, v0.w));
    float mb = fmaxf(fmaxf(v1.x, v1.y), fmaxf(v1.z, v1.w));
    float mc = fmaxf(fmaxf(v2.x, v2.y), fmaxf(v2.z, v2.w));
    float md = fmaxf(fmaxf(v3.x, v3.y), fmaxf(v3.z, v3.w));
    ma = fmaxf(ma, fmaxf(fmaxf(v4.x, v4.y), fmaxf(v4.z, v4.w)));
    mb = fmaxf(mb, fmaxf(fmaxf(v5.x, v5.y), fmaxf(v5.z, v5.w)));
    mc = fmaxf(mc, fmaxf(fmaxf(v6.x, v6.y), fmaxf(v6.z, v6.w)));
    md = fmaxf(md, fmaxf(fmaxf(v7.x, v7.y), fmaxf(v7.z, v7.w)));

    float s = (sa + sb) + (sc + sd);
    float m = fmaxf(fmaxf(ma, mb), fmaxf(mc, md));

    #pragma unroll
    for (int off = 16; off > 0; off >>= 1) {
        s += __shfl_xor_sync(0xFFFFFFFFu, s, off);
        m = fmaxf(m, __shfl_xor_sync(0xFFFFFFFFu, m, off));
    }
    if (lane == 0) {
        g_pm[gw] = s * (1.0f / (float)HW_DIM);
        g_px[gw] = m;
    }
}

// ---------------- Kernel B: grouped MLP ----------------
// block = 512 threads handles 8 blks (64 threads each), grid = NBLK/8 = 256
__global__ __launch_bounds__(512, 4)
void mlp_kernel(const float* __restrict__ w1,
                const float* __restrict__ w2,
                float* __restrict__ out)
{
    __shared__ float spm[8][C_DIM];
    __shared__ float spx[8][C_DIM];
    __shared__ float shs[8][C_DIM];

    const int tid = threadIdx.x;
    const int sub = tid >> 6;                  // which blk in this block (0..7)
    const int n   = tid & 63;                  // channel/hidden index
    const int blk = blockIdx.x * 8 + sub;
    const int o   = (blk / S_DIM) % O_DIM;

    spm[sub][n] = g_pm[blk * C_DIM + n];
    spx[sub][n] = g_px[blk * C_DIM + n];
    __syncthreads();

    // FC1 + relu (both pooled paths share W1)
    const float* w1r = w1 + ((size_t)o * C_DIM + n) * C_DIM;
    float am = 0.0f, ax = 0.0f;
    #pragma unroll
    for (int c = 0; c < C_DIM; ++c) {
        float w = __ldg(w1r + c);
        am = fmaf(spm[sub][c], w, am);
        ax = fmaf(spx[sub][c], w, ax);
    }
    shs[sub][n] = fmaxf(am, 0.0f) + fmaxf(ax, 0.0f);
    __syncthreads();

    // FC2 + sigmoid (linearity: single pass over summed hidden)
    const float* w2r = w2 + ((size_t)o * C_DIM + n) * C_DIM;
    float a = 0.0f;
    #pragma unroll
    for (int h = 0; h < C_DIM; ++h)
        a = fmaf(shs[sub][h], __ldg(w2r + h), a);
    out[(size_t)blk * C_DIM + n] = 1.0f / (1.0f + __expf(-a));
}

extern "C" void kernel_launch(void* const* d_in, const int* in_sizes, int n_in,
                              void* d_out, int out_size)
{
    const float* x  = (const float*)d_in[0];
    const float* w1 = (const float*)d_in[1];
    const float* w2 = (const float*)d_in[2];
    float* out = (float*)d_out;

    pool_kernel<<<NBLK * C_DIM / 8, 256>>>(x);
    mlp_kernel<<<NBLK / 8, 512>>>(w1, w2, out);
}

// round 5
// speedup vs baseline: 1.7451x; 1.7451x over previous
#include <cuda_runtime.h>
#include <math.h>

// ChannelAttention — R5: two-kernel split, fixed MLP weight coalescing.
//   Kernel A: streaming pool (mean+max) — one warp per (blk, channel).
//             (unchanged from R4: measured ~73 us = 7.0 TB/s, ~HBM roofline)
//   Kernel B: grouped MLP with weights staged in SMEM (coalesced loads,
//             padded rows for conflict-free compute).
// x  : [B=8, O=8, S=32, C=64, 32, 32] fp32 (512 MB)
// w1 : [8,64,64], w2 : [8,64,64] fp32
// out: [B,O,S,C] fp32

#define C_DIM   64
#define HW_DIM  1024
#define O_DIM   8
#define S_DIM   32
#define NBLK    2048            // B*O*S

__device__ float g_pm[NBLK * C_DIM];
__device__ float g_px[NBLK * C_DIM];

// ---------------- Kernel A: pooling (unchanged) ----------------
__global__ __launch_bounds__(256, 6)
void pool_kernel(const float* __restrict__ x)
{
    const int lane = threadIdx.x & 31;
    const int gw   = blockIdx.x * 8 + (threadIdx.x >> 5);  // global warp id
    const float4* row = reinterpret_cast<const float4*>(x) + (size_t)gw * (HW_DIM / 4) + lane;

    float4 v0 = __ldcs(row + 0 * 32);
    float4 v1 = __ldcs(row + 1 * 32);
    float4 v2 = __ldcs(row + 2 * 32);
    float4 v3 = __ldcs(row + 3 * 32);
    float4 v4 = __ldcs(row + 4 * 32);
    float4 v5 = __ldcs(row + 5 * 32);
    float4 v6 = __ldcs(row + 6 * 32);
    float4 v7 = __ldcs(row + 7 * 32);

    float sa = (v0.x + v0.y) + (v0.z + v0.w);
    float sb = (v1.x + v1.y) + (v1.z + v1.w);
    float sc = (v2.x + v2.y) + (v2.z + v2.w);
    float sd = (v3.x + v3.y) + (v3.z + v3.w);
    sa += (v4.x + v4.y) + (v4.z + v4.w);
    sb += (v5.x + v5.y) + (v5.z + v5.w);
    sc += (v6.x + v6.y) + (v6.z + v6.w);
    sd += (v7.x + v7.y) + (v7.z + v7.w);

    float ma = fmaxf(fmaxf(v0.x, v0.y), fmaxf(v0.z, v0.w));
    float mb = fmaxf(fmaxf(v1.x, v1.y), fmaxf(v1.z, v1.w));
    float mc = fmaxf(fmaxf(v2.x, v2.y), fmaxf(v2.z, v2.w));
    float md = fmaxf(fmaxf(v3.x, v3.y), fmaxf(v3.z, v3.w));
    ma = fmaxf(ma, fmaxf(fmaxf(v4.x, v4.y), fmaxf(v4.z, v4.w)));
    mb = fmaxf(mb, fmaxf(fmaxf(v5.x, v5.y), fmaxf(v5.z, v5.w)));
    mc = fmaxf(mc, fmaxf(fmaxf(v6.x, v6.y), fmaxf(v6.z, v6.w)));
    md = fmaxf(md, fmaxf(fmaxf(v7.x, v7.y), fmaxf(v7.z, v7.w)));

    float s = (sa + sb) + (sc + sd);
    float m = fmaxf(fmaxf(ma, mb), fmaxf(mc, md));

    #pragma unroll
    for (int off = 16; off > 0; off >>= 1) {
        s += __shfl_xor_sync(0xFFFFFFFFu, s, off);
        m = fmaxf(m, __shfl_xor_sync(0xFFFFFFFFu, m, off));
    }
    if (lane == 0) {
        g_pm[gw] = s * (1.0f / (float)HW_DIM);
        g_px[gw] = m;
    }
}

// ---------------- Kernel B: grouped MLP (smem-staged weights) ----------------
// grid = 256 blocks, 512 threads. Block handles 8 consecutive blks (same o,
// since 8 | 32 = S). Weights for group o staged in smem, coalesced.
#define WPAD 65   // 64 + 1: n*65+c mod 32 distinct across lanes -> conflict-free

__global__ __launch_bounds__(512, 2)
void mlp_kernel(const float* __restrict__ w1,
                const float* __restrict__ w2,
                float* __restrict__ out)
{
    __shared__ float w1s[C_DIM * WPAD];
    __shared__ float w2s[C_DIM * WPAD];
    __shared__ float spm[8][C_DIM];
    __shared__ float spx[8][C_DIM];
    __shared__ float shs[8][C_DIM];

    const int tid = threadIdx.x;
    const int sub = tid >> 6;                  // blk within block (0..7)
    const int n   = tid & 63;                  // output/hidden index
    const int blk = blockIdx.x * 8 + sub;
    const int o   = (blk / S_DIM) % O_DIM;     // same for all 8 subs

    // ---- stage weights: coalesced global reads, padded smem rows ----
    const float* w1g = w1 + (size_t)o * C_DIM * C_DIM;
    const float* w2g = w2 + (size_t)o * C_DIM * C_DIM;
    #pragma unroll
    for (int i = 0; i < 8; ++i) {
        int idx = tid + i * 512;               // 0..4095, contiguous per step
        int r = idx >> 6, c = idx & 63;
        w1s[r * WPAD + c] = __ldg(w1g + idx);
        w2s[r * WPAD + c] = __ldg(w2g + idx);
    }

    // ---- stage pooled inputs (coalesced: 512 consecutive floats) ----
    spm[sub][n] = g_pm[blk * C_DIM + n];
    spx[sub][n] = g_px[blk * C_DIM + n];
    __syncthreads();

    // ---- FC1 + relu: thread (sub, n) -> hidden n of blk ----
    const float* w1r = &w1s[n * WPAD];
    float am = 0.0f, ax = 0.0f;
    #pragma unroll
    for (int c = 0; c < C_DIM; ++c) {
        float w = w1r[c];                      // conflict-free (stride-1 banks)
        am = fmaf(spm[sub][c], w, am);         // broadcast
        ax = fmaf(spx[sub][c], w, ax);         // broadcast
    }
    shs[sub][n] = fmaxf(am, 0.0f) + fmaxf(ax, 0.0f);
    __syncthreads();

    // ---- FC2 + sigmoid (linearity: single pass over summed hidden) ----
    const float* w2r = &w2s[n * WPAD];
    float a = 0.0f;
    #pragma unroll
    for (int h = 0; h < C_DIM; ++h)
        a = fmaf(shs[sub][h], w2r[h], a);
    out[(size_t)blk * C_DIM + n] = 1.0f / (1.0f + __expf(-a));
}

extern "C" void kernel_launch(void* const* d_in, const int* in_sizes, int n_in,
                              void* d_out, int out_size)
{
    const float* x  = (const float*)d_in[0];
    const float* w1 = (const float*)d_in[1];
    const float* w2 = (const float*)d_in[2];
    float* out = (float*)d_out;

    pool_kernel<<<NBLK * C_DIM / 8, 256>>>(x);
    mlp_kernel<<<NBLK / 8, 512>>>(w1, w2, out);
}